// round 8
// baseline (speedup 1.0000x reference)
#include <cuda_runtime.h>
#include <cuda_bf16.h>
#include <math.h>
#include <stdint.h>

// ---------------- problem constants ----------------
#define BATCH 8
#define TSTEPS 16
#define CIN0 192
#define HC0 64
#define HC1 32
#define HC2 64
#define IMG_H 28
#define IMG_W 28
#define HW 784

#define GRID_N 592           // 148 SMs x 4 blocks; residency required for barrier
#define NTASKS 1568

// ---------------- device scratch (no allocs allowed) ----------------
__device__ float g_gx0[(size_t)BATCH * TSTEPS * 4 * HC0 * HW];

#define SZ0 (BATCH * HC0 * HW)
#define SZ1 (BATCH * HC1 * HW)
#define SZ2 (BATCH * HC2 * HW)
#define OFF_H0A 0
#define OFF_H0B (OFF_H0A + SZ0)
#define OFF_C0  (OFF_H0B + SZ0)
#define OFF_H1A (OFF_C0  + SZ0)
#define OFF_H1B (OFF_H1A + SZ1)
#define OFF_C1  (OFF_H1B + SZ1)
#define OFF_H2A (OFF_C1  + SZ1)
#define OFF_H2B (OFF_H2A + SZ2)
#define OFF_C2  (OFF_H2B + SZ2)
#define NSTATE  (OFF_C2  + SZ2)
__device__ float g_state[NSTATE];

// pre-transposed tf32 weight buffers, layout [y][chunk][tap][m(32)][ci(8)]
#define WPC 2304
#define WOFF_GX0 0
#define WSZ_GX0 (8 * 24 * WPC)
#define WOFF_L0 (WOFF_GX0 + WSZ_GX0)
#define WSZ_L0  (8 * 8 * WPC)
#define WOFF_L1 (WOFF_L0 + WSZ_L0)
#define WSZ_L1  (4 * 12 * WPC)
#define WOFF_L2 (WOFF_L1 + WSZ_L1)
#define WSZ_L2  (8 * 12 * WPC)
#define WTOTAL  (WOFF_L2 + WSZ_L2)
__device__ uint32_t g_wt[WTOTAL];

// grid barrier state (monotonic generation; safe across graph replays)
__device__ unsigned g_bar_count;
__device__ unsigned g_bar_gen;

// ---------------- tf32 helpers ----------------
__device__ __forceinline__ uint32_t f2tf32(float f) {
    uint32_t u;
    asm("cvt.rna.tf32.f32 %0, %1;" : "=r"(u) : "f"(f));
    return u;
}

__device__ __forceinline__ void mma_tf32(float c[4],
                                         uint32_t a0, uint32_t a1, uint32_t a2, uint32_t a3,
                                         uint32_t b0, uint32_t b1) {
    asm volatile(
        "mma.sync.aligned.m16n8k8.row.col.f32.tf32.tf32.f32 "
        "{%0,%1,%2,%3}, {%4,%5,%6,%7}, {%8,%9}, {%0,%1,%2,%3};"
        : "+f"(c[0]), "+f"(c[1]), "+f"(c[2]), "+f"(c[3])
        : "r"(a0), "r"(a1), "r"(a2), "r"(a3), "r"(b0), "r"(b1));
}

__device__ __forceinline__ float sigmoidf_(float x) {
    return 1.0f / (1.0f + __expf(-x));
}

// ---------------- grid barrier ----------------
__device__ __forceinline__ void grid_barrier() {
    __syncthreads();
    if (threadIdx.x == 0) {
        unsigned gen = *(volatile unsigned*)&g_bar_gen;
        __threadfence();
        unsigned a = atomicAdd(&g_bar_count, 1u);
        if (a == GRID_N - 1) {
            *(volatile unsigned*)&g_bar_count = 0u;
            __threadfence();
            atomicAdd(&g_bar_gen, 1u);
        } else {
            while (*(volatile unsigned*)&g_bar_gen == gen) { __nanosleep(64); }
            __threadfence();
        }
    }
    __syncthreads();
}

// ---------------- weight prep (device, grid-stride) ----------------
__device__ void prep_set(const float* __restrict__ WA, int cinA,
                         const float* __restrict__ WB, int cinB,
                         int HC, int chunks, uint32_t* __restrict__ dst, int total,
                         int gtid, int gstride)
{
    for (int idx = gtid; idx < total; idx += gstride) {
        int ci  = idx & 7;
        int m   = (idx >> 3) & 31;
        int tap = (idx >> 8) % 9;
        int chy = idx / WPC;
        int ch  = chy % chunks;
        int y   = chy / chunks;
        int oc  = (m >> 3) * HC + y * 8 + (m & 7);
        int cg  = ch * 8 + ci;
        float w;
        if (cg < cinA) w = WA[((size_t)oc * cinA + cg) * 9 + tap];
        else           w = WB[((size_t)oc * cinB + (cg - cinA)) * 9 + tap];
        dst[idx] = f2tf32(w);
    }
}

// ---------------- conv 3x3 + fused LSTM body ----------------
#define SIN_STR 200

struct SmemU {
    union {
        struct {
            uint32_t in[2][8 * SIN_STR];
            uint32_t w[2][WPC];
        } mm;
        float gates[4 * 8 * 112];
    };
};

__device__ __forceinline__ void conv_cell_body(
    SmemU& sm,
    int n, int yb, int rowbase,
    const float* __restrict__ inA, int cinA, size_t inAStride,
    const float* __restrict__ inB, int cinB,
    const uint32_t* __restrict__ wt,
    const float* __restrict__ bias,
    const float* __restrict__ pre, size_t preStride,
    int HC,
    float* __restrict__ out, size_t outStride,   // plain path (hout == nullptr)
    const float* __restrict__ Wp,
    float* __restrict__ hout, float* __restrict__ c,
    float* __restrict__ yout, int t)
{
    const int hcb = yb * 8;

    const int tid    = threadIdx.x;
    const int lane   = tid & 31;
    const int wid    = tid >> 5;
    const int warp_m = wid & 1;
    const int warp_n = wid >> 1;
    const int g      = lane >> 2;
    const int ctg    = lane & 3;

    const int chunks = (cinA + cinB) >> 3;

    int off[7];
#pragma unroll
    for (int s = 0; s < 7; ++s) {
        int nl = warp_n * 56 + s * 8 + g;
        int r = nl / 28;
        off[s] = r * 30 + (nl - r * 28);
    }

    float acc[7][4];
#pragma unroll
    for (int s = 0; s < 7; ++s)
#pragma unroll
        for (int j = 0; j < 4; ++j) acc[s][j] = 0.f;

    float rin[12];
    uint4 rw4[5];

    auto load_chunk = [&](int ch) {
        const int cstart = ch * 8;
        const float* src = (cstart < cinA)
            ? inA + (size_t)n * inAStride + (size_t)cstart * HW
            : inB + ((size_t)n * cinB + (cstart - cinA)) * HW;
#pragma unroll
        for (int k = 0; k < 12; ++k) {
            int idx = tid + k * 128;
            float v = 0.f;
            if (idx < 1440) {
                int ci  = idx / 180;
                int rem = idx - ci * 180;
                int pr  = rem / 30;
                int gr  = rowbase + pr - 1;
                int gc  = (rem - pr * 30) - 1;
                if (gr >= 0 && gr < IMG_H && gc >= 0 && gc < IMG_W)
                    v = src[(size_t)ci * HW + gr * IMG_W + gc];
            }
            rin[k] = v;
        }
        const uint4* wsrc = (const uint4*)(wt + ((size_t)yb * chunks + ch) * WPC);
#pragma unroll
        for (int k = 0; k < 5; ++k) {
            int i4 = tid + k * 128;
            if (i4 < 576) rw4[k] = wsrc[i4];
        }
    };

    load_chunk(0);

    for (int ch = 0; ch < chunks; ++ch) {
        const int st = ch & 1;
#pragma unroll
        for (int k = 0; k < 12; ++k) {
            int idx = tid + k * 128;
            if (idx < 1440) {
                int ci  = idx / 180;
                int rem = idx - ci * 180;
                sm.mm.in[st][ci * SIN_STR + rem] = f2tf32(rin[k]);
            }
        }
#pragma unroll
        for (int k = 0; k < 5; ++k) {
            int i4 = tid + k * 128;
            if (i4 < 576) ((uint4*)sm.mm.w[st])[i4] = rw4[k];
        }
        __syncthreads();

        if (ch + 1 < chunks) load_chunk(ch + 1);

        const uint32_t* win = sm.mm.in[st];
        const uint32_t* ww  = sm.mm.w[st];
#pragma unroll
        for (int kr = 0; kr < 3; ++kr) {
#pragma unroll
            for (int kc = 0; kc < 3; ++kc) {
                const int tap = kr * 3 + kc;
                const uint32_t* wp = ww + tap * 256 + (warp_m * 16 + g) * 8 + ctg;
                uint32_t a0 = wp[0];
                uint32_t a1 = wp[64];
                uint32_t a2 = wp[4];
                uint32_t a3 = wp[68];
                const int bbase = ctg * SIN_STR + kr * 30 + kc;
#pragma unroll
                for (int s = 0; s < 7; ++s) {
                    uint32_t b0 = win[bbase + off[s]];
                    uint32_t b1 = win[bbase + off[s] + 4 * SIN_STR];
                    mma_tf32(acc[s], a0, a1, a2, a3, b0, b1);
                }
            }
        }
    }

    // ---- epilogue ----
    const int m0  = warp_m * 16 + g;
    const int oc0 = (m0 >> 3) * HC + hcb + (m0 & 7);
    const int m1  = m0 + 8;
    const int oc1 = (m1 >> 3) * HC + hcb + (m1 & 7);
    float bv0 = 0.f, bv1 = 0.f;
    if (bias) { bv0 = bias[oc0]; bv1 = bias[oc1]; }

    if (hout == nullptr) {
#pragma unroll
        for (int s = 0; s < 7; ++s) {
#pragma unroll
            for (int j = 0; j < 2; ++j) {
                int nl = warp_n * 56 + s * 8 + 2 * ctg + j;
                int r = nl / 28;
                int px = (rowbase + r) * IMG_W + (nl - r * 28);
                float v0 = acc[s][j]     + bv0;
                float v1 = acc[s][2 + j] + bv1;
                if (pre) {
                    v0 += pre[(size_t)n * preStride + (size_t)oc0 * HW + px];
                    v1 += pre[(size_t)n * preStride + (size_t)oc1 * HW + px];
                }
                out[(size_t)n * outStride + (size_t)oc0 * HW + px] = v0;
                out[(size_t)n * outStride + (size_t)oc1 * HW + px] = v1;
            }
        }
        return;
    }

    __syncthreads();
#pragma unroll
    for (int s = 0; s < 7; ++s) {
#pragma unroll
        for (int j = 0; j < 2; ++j) {
            int nl = warp_n * 56 + s * 8 + 2 * ctg + j;
            float v0 = acc[s][j]     + bv0;
            float v1 = acc[s][2 + j] + bv1;
            if (pre) {
                int r = nl / 28;
                int px = (rowbase + r) * IMG_W + (nl - r * 28);
                v0 += pre[(size_t)n * preStride + (size_t)oc0 * HW + px];
                v1 += pre[(size_t)n * preStride + (size_t)oc1 * HW + px];
            }
            sm.gates[((m0 >> 3) * 8 + (m0 & 7)) * 112 + nl] = v0;
            sm.gates[((m1 >> 3) * 8 + (m1 & 7)) * 112 + nl] = v1;
        }
    }
    __syncthreads();

#pragma unroll
    for (int k = 0; k < 7; ++k) {
        int e   = tid + k * 128;
        int hcl = e / 112;
        int nl  = e - hcl * 112;
        int r   = nl / 28;
        int px  = (rowbase + r) * IMG_W + (nl - r * 28);
        int hc  = hcb + hcl;

        float g0 = sm.gates[(0 * 8 + hcl) * 112 + nl];
        float g1 = sm.gates[(1 * 8 + hcl) * 112 + nl];
        float g2 = sm.gates[(2 * 8 + hcl) * 112 + nl];
        float g3 = sm.gates[(3 * 8 + hcl) * 112 + nl];

        size_t sidx = ((size_t)n * HC + hc) * HW + px;
        float cv = c[sidx];
        float pi = Wp[(size_t)(0 * HC + hc) * HW + px];
        float pf = Wp[(size_t)(1 * HC + hc) * HW + px];
        float po = Wp[(size_t)(2 * HC + hc) * HW + px];

        float gi = sigmoidf_(g0 + cv * pi);
        float gf = sigmoidf_(g1 + cv * pf);
        float cc = gf * cv + gi * tanhf(g2);
        float go = sigmoidf_(g3 + cc * po);
        float hv = go * tanhf(cc);

        c[sidx] = cc;
        hout[sidx] = hv;
        if (yout)
            yout[(((size_t)n * TSTEPS + t) * HC + hc) * HW + px] = hv;
    }
}

// ---------------- task dispatch: L0(s) | gx0(s+1) | L1(s-1) | L2(s-2) --------
#define GX0_FRAME ((size_t)4 * HC0 * HW)
#define GX0_BSTR  ((size_t)TSTEPS * 4 * HC0 * HW)

__device__ void do_task(
    SmemU& sm, int s, int taskid,
    const float* __restrict__ x,
    float* __restrict__ gx0,
    float* __restrict__ state,
    const uint32_t* __restrict__ wt,
    const float* __restrict__ bx0, const float* __restrict__ bx1, const float* __restrict__ bx2,
    const float* __restrict__ Wp0, const float* __restrict__ Wp1, const float* __restrict__ Wp2,
    float* __restrict__ y)
{
    float* h0buf[2] = { state + OFF_H0A, state + OFF_H0B };
    float* h1buf[2] = { state + OFF_H1A, state + OFF_H1B };
    float* h2buf[2] = { state + OFF_H2A, state + OFF_H2B };

    if (taskid < 448) {
        const int t = s;
        if (t < 0 || t >= TSTEPS) return;
        int local = taskid;
        int z = local % 7; local /= 7;
        int yb = local % 8;
        int n  = local / 8;
        const int rb = t & 1, wb = rb ^ 1;
        conv_cell_body(sm, n, yb, z * 4,
                       h0buf[rb], HC0, (size_t)HC0 * HW, nullptr, 0,
                       wt + WOFF_L0, nullptr,
                       gx0 + (size_t)t * GX0_FRAME, GX0_BSTR,
                       HC0, nullptr, 0,
                       Wp0, h0buf[wb], state + OFF_C0, nullptr, t);
    } else if (taskid < 896) {
        const int t = s + 1;
        if (t < 0 || t >= TSTEPS) return;
        int local = taskid - 448;
        int z = local % 7; local /= 7;
        int yb = local % 8;
        int n  = local / 8;
        conv_cell_body(sm, n, yb, z * 4,
                       x + (size_t)t * CIN0 * HW, CIN0, (size_t)TSTEPS * CIN0 * HW,
                       nullptr, 0,
                       wt + WOFF_GX0, bx0, nullptr, 0,
                       HC0, gx0 + (size_t)t * GX0_FRAME, GX0_BSTR,
                       nullptr, nullptr, nullptr, nullptr, t);
    } else if (taskid < 1120) {
        const int t = s - 1;
        if (t < 0 || t >= TSTEPS) return;
        int local = taskid - 896;
        int z = local % 7; local /= 7;
        int yb = local % 4;
        int n  = local / 4;
        const int rb = t & 1, wb = rb ^ 1;
        conv_cell_body(sm, n, yb, z * 4,
                       h0buf[wb], HC0, (size_t)HC0 * HW,   // h0(t), written at wave s-1
                       h1buf[rb], HC1,
                       wt + WOFF_L1, bx1, nullptr, 0,
                       HC1, nullptr, 0,
                       Wp1, h1buf[wb], state + OFF_C1, nullptr, t);
    } else {
        const int t = s - 2;
        if (t < 0 || t >= TSTEPS) return;
        int local = taskid - 1120;
        int z = local % 7; local /= 7;
        int yb = local % 8;
        int n  = local / 8;
        const int rb = t & 1, wb = rb ^ 1;
        conv_cell_body(sm, n, yb, z * 4,
                       h1buf[wb], HC1, (size_t)HC1 * HW,   // h1(t), written at wave s-1
                       h2buf[rb], HC2,
                       wt + WOFF_L2, bx2, nullptr, 0,
                       HC2, nullptr, 0,
                       Wp2, h2buf[wb], state + OFF_C2, y, t);
    }
}

// ---------------- persistent kernel: init + 19 waves, grid barriers ----------
__global__ void __launch_bounds__(128, 4) convlstm_persistent(
    const float* __restrict__ x,
    const float* __restrict__ Wx0, const float* __restrict__ bx0,
    const float* __restrict__ Wh0, const float* __restrict__ Wp0,
    const float* __restrict__ Wx1, const float* __restrict__ bx1,
    const float* __restrict__ Wh1, const float* __restrict__ Wp1,
    const float* __restrict__ Wx2, const float* __restrict__ bx2,
    const float* __restrict__ Wh2, const float* __restrict__ Wp2,
    float* __restrict__ y)
{
    __shared__ SmemU sm;

    float* gx0   = g_gx0;
    float* state = g_state;
    uint32_t* wt = g_wt;

    const int gtid    = blockIdx.x * blockDim.x + threadIdx.x;
    const int gstride = GRID_N * 128;

    // ---- init: zero state, prep transposed tf32 weights ----
    for (int i = gtid; i < NSTATE; i += gstride) state[i] = 0.f;
    prep_set(Wx0, CIN0, nullptr, 0, HC0, 24, wt + WOFF_GX0, WSZ_GX0, gtid, gstride);
    prep_set(Wh0, HC0,  nullptr, 0, HC0,  8, wt + WOFF_L0,  WSZ_L0,  gtid, gstride);
    prep_set(Wx1, HC0,  Wh1, HC1, HC1, 12, wt + WOFF_L1,  WSZ_L1,  gtid, gstride);
    prep_set(Wx2, HC1,  Wh2, HC2, HC2, 12, wt + WOFF_L2,  WSZ_L2,  gtid, gstride);
    grid_barrier();

    // ---- waves ----
    for (int s = -1; s <= 17; ++s) {
#pragma unroll 1
        for (int k = 0; k < 3; ++k) {
            int tt = blockIdx.x + k * GRID_N;
            if (tt < NTASKS)
                do_task(sm, s, tt, x, gx0, state, wt,
                        bx0, bx1, bx2, Wp0, Wp1, Wp2, y);
            __syncthreads();
        }
        if (s < 17) grid_barrier();
    }
}

// ---------------- host launch: ONE kernel ----------------
extern "C" void kernel_launch(void* const* d_in, const int* in_sizes, int n_in,
                              void* d_out, int out_size)
{
    const float* x   = (const float*)d_in[0];
    const float* Wx0 = (const float*)d_in[1];
    const float* bx0 = (const float*)d_in[2];
    const float* Wh0 = (const float*)d_in[3];
    const float* Wp0 = (const float*)d_in[4];
    const float* Wx1 = (const float*)d_in[5];
    const float* bx1 = (const float*)d_in[6];
    const float* Wh1 = (const float*)d_in[7];
    const float* Wp1 = (const float*)d_in[8];
    const float* Wx2 = (const float*)d_in[9];
    const float* bx2 = (const float*)d_in[10];
    const float* Wh2 = (const float*)d_in[11];
    const float* Wp2 = (const float*)d_in[12];
    float* y = (float*)d_out;

    convlstm_persistent<<<GRID_N, 128>>>(
        x, Wx0, bx0, Wh0, Wp0, Wx1, bx1, Wh1, Wp1, Wx2, bx2, Wh2, Wp2, y);
}

// round 9
// speedup vs baseline: 1.3431x; 1.3431x over previous
#include <cuda_runtime.h>
#include <cuda_bf16.h>
#include <math.h>
#include <stdint.h>

// ---------------- problem constants ----------------
#define BATCH 8
#define TSTEPS 16
#define CIN0 192
#define HC0 64
#define HC1 32
#define HC2 64
#define IMG_H 28
#define IMG_W 28
#define HW 784

// ---------------- device scratch (no allocs allowed) ----------------
__device__ float g_gx0[(size_t)BATCH * TSTEPS * 4 * HC0 * HW];
__device__ float g_xtf[(size_t)BATCH * TSTEPS * CIN0 * HW];   // tf32-rounded x

// double-buffered h (a/b) + single c per layer
#define SZ0 (BATCH * HC0 * HW)
#define SZ1 (BATCH * HC1 * HW)
#define SZ2 (BATCH * HC2 * HW)
#define OFF_H0A 0
#define OFF_H0B (OFF_H0A + SZ0)
#define OFF_C0  (OFF_H0B + SZ0)
#define OFF_H1A (OFF_C0  + SZ0)
#define OFF_H1B (OFF_H1A + SZ1)
#define OFF_C1  (OFF_H1B + SZ1)
#define OFF_H2A (OFF_C1  + SZ1)
#define OFF_H2B (OFF_H2A + SZ2)
#define OFF_C2  (OFF_H2B + SZ2)
#define NSTATE  (OFF_C2  + SZ2)
__device__ float g_state[NSTATE];

// pre-transposed tf32 weight buffers, layout [y][chunk][tap][m(32)][ci(8)]
#define WPC 2304
#define WOFF_GX0 0
#define WSZ_GX0 (8 * 24 * WPC)
#define WOFF_L0 (WOFF_GX0 + WSZ_GX0)
#define WSZ_L0  (8 * 8 * WPC)
#define WOFF_L1 (WOFF_L0 + WSZ_L0)
#define WSZ_L1  (4 * 12 * WPC)
#define WOFF_L2 (WOFF_L1 + WSZ_L1)
#define WSZ_L2  (8 * 12 * WPC)
#define WTOTAL  (WOFF_L2 + WSZ_L2)
__device__ uint32_t g_wt[WTOTAL];

__global__ void init_zero_kernel(float* p, int n) {
    int i = blockIdx.x * blockDim.x + threadIdx.x;
    if (i < n) p[i] = 0.f;
}

// ---------------- tf32 / cp.async helpers ----------------
__device__ __forceinline__ uint32_t f2tf32(float f) {
    uint32_t u;
    asm("cvt.rna.tf32.f32 %0, %1;" : "=r"(u) : "f"(f));
    return u;
}

__device__ __forceinline__ void cp_async16(uint32_t saddr, const void* gaddr) {
    asm volatile("cp.async.cg.shared.global [%0], [%1], 16;" :: "r"(saddr), "l"(gaddr));
}
#define CP_ASYNC_COMMIT() asm volatile("cp.async.commit_group;" ::: "memory")
#define CP_ASYNC_WAIT0()  asm volatile("cp.async.wait_group 0;" ::: "memory")

__device__ __forceinline__ void mma_tf32(float c[4],
                                         uint32_t a0, uint32_t a1, uint32_t a2, uint32_t a3,
                                         uint32_t b0, uint32_t b1) {
    asm volatile(
        "mma.sync.aligned.m16n8k8.row.col.f32.tf32.tf32.f32 "
        "{%0,%1,%2,%3}, {%4,%5,%6,%7}, {%8,%9}, {%0,%1,%2,%3};"
        : "+f"(c[0]), "+f"(c[1]), "+f"(c[2]), "+f"(c[3])
        : "r"(a0), "r"(a1), "r"(a2), "r"(a3), "r"(b0), "r"(b1));
}

__device__ __forceinline__ float sigmoidf_(float x) {
    return 1.0f / (1.0f + __expf(-x));
}

// ---------------- prep kernels ----------------
__global__ void prep_weights(const float* __restrict__ WA, int cinA,
                             const float* __restrict__ WB, int cinB,
                             int HC, int chunks, uint32_t* __restrict__ dst, int total)
{
    int idx = blockIdx.x * blockDim.x + threadIdx.x;
    if (idx >= total) return;
    int ci  = idx & 7;
    int m   = (idx >> 3) & 31;
    int tap = (idx >> 8) % 9;
    int chy = idx / WPC;
    int ch  = chy % chunks;
    int y   = chy / chunks;
    int oc  = (m >> 3) * HC + y * 8 + (m & 7);
    int cg  = ch * 8 + ci;
    float w;
    if (cg < cinA) w = WA[((size_t)oc * cinA + cg) * 9 + tap];
    else           w = WB[((size_t)oc * cinB + (cg - cinA)) * 9 + tap];
    dst[idx] = f2tf32(w);
}

__global__ void prep_x(const float* __restrict__ x, float* __restrict__ xtf, int n) {
    int i = blockIdx.x * blockDim.x + threadIdx.x;
    if (i < n) xtf[i] = __uint_as_float(f2tf32(x[i]));
}

// ---------------- conv 3x3 + fused LSTM ----------------
// Block: 64 threads = 2 warps, both in N (56 px each). M=32 per WARP:
// two A fragments per tap -> 2 MMAs per B fragment (halves B smem traffic/MMA).
// m -> oc = (m>>3)*HC + yb*8 + (m&7). Inputs must be tf32-rounded floats.
#define SIN_STR 200

struct SmemU {
    union {
        struct {
            uint32_t in[2][8 * SIN_STR];
            uint32_t w[2][WPC];
        } mm;
        float gates[4 * 8 * 112];
    };
};

__global__ void __launch_bounds__(64, 7) conv3x3_cell(
    const float* __restrict__ inA, int cinA, size_t inAStride,
    const float* __restrict__ inB, int cinB,
    const uint32_t* __restrict__ wt,
    const float* __restrict__ bias,
    const float* __restrict__ pre, size_t preStride,
    int HC,
    float* __restrict__ out, size_t outStride,   // plain path (hout == nullptr)
    const float* __restrict__ Wp,
    float* __restrict__ hout, float* __restrict__ c,
    float* __restrict__ yout, int t)
{
    __shared__ SmemU sm;

    const int n       = blockIdx.x;
    const int yb      = blockIdx.y;
    const int hcb     = yb * 8;
    const int rowbase = blockIdx.z * 4;

    const int tid  = threadIdx.x;
    const int lane = tid & 31;
    const int wid  = tid >> 5;      // warp_n (0/1)
    const int g    = lane >> 2;
    const int ctg  = lane & 3;

    const int chunks = (cinA + cinB) >> 3;

    uint32_t wsm[2];
    wsm[0] = (uint32_t)__cvta_generic_to_shared(sm.mm.w[0]);
    wsm[1] = (uint32_t)__cvta_generic_to_shared(sm.mm.w[1]);

    int off[7];
#pragma unroll
    for (int s = 0; s < 7; ++s) {
        int nl = wid * 56 + s * 8 + g;
        int r = nl / 28;
        off[s] = r * 30 + (nl - r * 28);
    }

    float acc[7][8];
#pragma unroll
    for (int s = 0; s < 7; ++s)
#pragma unroll
        for (int j = 0; j < 8; ++j) acc[s][j] = 0.f;

    float rin[23];

    auto load_chunk = [&](int ch) {
        const int st = ch & 1;
        const int cstart = ch * 8;
        const float* src = (cstart < cinA)
            ? inA + (size_t)n * inAStride + (size_t)cstart * HW
            : inB + ((size_t)n * cinB + (cstart - cinA)) * HW;
#pragma unroll
        for (int k = 0; k < 23; ++k) {
            int idx = tid + k * 64;
            float v = 0.f;
            if (idx < 1440) {
                int ci  = idx / 180;
                int rem = idx - ci * 180;
                int pr  = rem / 30;
                int gr  = rowbase + pr - 1;
                int gc  = (rem - pr * 30) - 1;
                if (gr >= 0 && gr < IMG_H && gc >= 0 && gc < IMG_W)
                    v = src[(size_t)ci * HW + gr * IMG_W + gc];
            }
            rin[k] = v;
        }
        const char* wsrc = (const char*)(wt + ((size_t)yb * chunks + ch) * WPC);
#pragma unroll
        for (int k = 0; k < 9; ++k) {
            int i4 = tid + k * 64;
            if (i4 < 576) cp_async16(wsm[st] + i4 * 16, wsrc + (size_t)i4 * 16);
        }
        CP_ASYNC_COMMIT();
    };

    load_chunk(0);

    for (int ch = 0; ch < chunks; ++ch) {
        const int st = ch & 1;
#pragma unroll
        for (int k = 0; k < 23; ++k) {
            int idx = tid + k * 64;
            if (idx < 1440) {
                int ci  = idx / 180;
                int rem = idx - ci * 180;
                sm.mm.in[st][ci * SIN_STR + rem] = __float_as_uint(rin[k]);
            }
        }
        CP_ASYNC_WAIT0();        // weights for chunk ch landed
        __syncthreads();

        if (ch + 1 < chunks) load_chunk(ch + 1);   // overlaps MMA phase

        const uint32_t* win = sm.mm.in[st];
        const uint32_t* ww  = sm.mm.w[st];
#pragma unroll
        for (int kr = 0; kr < 3; ++kr) {
#pragma unroll
            for (int kc = 0; kc < 3; ++kc) {
                const int tap = kr * 3 + kc;
                const uint32_t* wp = ww + tap * 256 + g * 8 + ctg;
                uint32_t a00 = wp[0],   a01 = wp[64],  a02 = wp[4],   a03 = wp[68];
                uint32_t a10 = wp[128], a11 = wp[192], a12 = wp[132], a13 = wp[196];
                const int bbase = ctg * SIN_STR + kr * 30 + kc;
#pragma unroll
                for (int s = 0; s < 7; ++s) {
                    uint32_t b0 = win[bbase + off[s]];
                    uint32_t b1 = win[bbase + off[s] + 4 * SIN_STR];
                    mma_tf32(acc[s],     a00, a01, a02, a03, b0, b1);
                    mma_tf32(acc[s] + 4, a10, a11, a12, a13, b0, b1);
                }
            }
        }
    }

    // ---- epilogue: thread owns rows m={g, g+8, 16+g, 24+g} = gates 0..3, hcl=g
    int ocr[4];
    float bv[4];
#pragma unroll
    for (int gate = 0; gate < 4; ++gate) {
        ocr[gate] = gate * HC + hcb + g;
        bv[gate]  = bias ? bias[ocr[gate]] : 0.f;
    }

    if (hout == nullptr) {
#pragma unroll
        for (int s = 0; s < 7; ++s) {
#pragma unroll
            for (int j = 0; j < 2; ++j) {
                int nl = wid * 56 + s * 8 + 2 * ctg + j;
                int r = nl / 28;
                int px = (rowbase + r) * IMG_W + (nl - r * 28);
#pragma unroll
                for (int f = 0; f < 2; ++f) {
                    float vlo = acc[s][f * 4 + j]     + bv[2 * f];
                    float vhi = acc[s][f * 4 + 2 + j] + bv[2 * f + 1];
                    if (pre) {
                        vlo += pre[(size_t)n * preStride + (size_t)ocr[2 * f]     * HW + px];
                        vhi += pre[(size_t)n * preStride + (size_t)ocr[2 * f + 1] * HW + px];
                    }
                    out[(size_t)n * outStride + (size_t)ocr[2 * f]     * HW + px] = vlo;
                    out[(size_t)n * outStride + (size_t)ocr[2 * f + 1] * HW + px] = vhi;
                }
            }
        }
        return;
    }

    // fused LSTM: exchange gates through smem, then pointwise
    __syncthreads();   // all MMA reads done before union overwrite
#pragma unroll
    for (int s = 0; s < 7; ++s) {
#pragma unroll
        for (int j = 0; j < 2; ++j) {
            int nl = wid * 56 + s * 8 + 2 * ctg + j;
            int r = nl / 28;
            int px = (rowbase + r) * IMG_W + (nl - r * 28);
#pragma unroll
            for (int f = 0; f < 2; ++f) {
                float vlo = acc[s][f * 4 + j]     + bv[2 * f];
                float vhi = acc[s][f * 4 + 2 + j] + bv[2 * f + 1];
                if (pre) {
                    vlo += pre[(size_t)n * preStride + (size_t)ocr[2 * f]     * HW + px];
                    vhi += pre[(size_t)n * preStride + (size_t)ocr[2 * f + 1] * HW + px];
                }
                sm.gates[((2 * f)     * 8 + g) * 112 + nl] = vlo;
                sm.gates[((2 * f + 1) * 8 + g) * 112 + nl] = vhi;
            }
        }
    }
    __syncthreads();

    // pointwise over 8 hc x 112 px  (896 elems, 14 per thread)
#pragma unroll
    for (int k = 0; k < 14; ++k) {
        int e   = tid + k * 64;
        int hcl = e / 112;
        int nl  = e - hcl * 112;
        int r   = nl / 28;
        int px  = (rowbase + r) * IMG_W + (nl - r * 28);
        int hc  = hcb + hcl;

        float g0 = sm.gates[(0 * 8 + hcl) * 112 + nl];
        float g1 = sm.gates[(1 * 8 + hcl) * 112 + nl];
        float g2 = sm.gates[(2 * 8 + hcl) * 112 + nl];
        float g3 = sm.gates[(3 * 8 + hcl) * 112 + nl];

        size_t sidx = ((size_t)n * HC + hc) * HW + px;
        float cv = c[sidx];
        float pi = Wp[(size_t)(0 * HC + hc) * HW + px];
        float pf = Wp[(size_t)(1 * HC + hc) * HW + px];
        float po = Wp[(size_t)(2 * HC + hc) * HW + px];

        float gi = sigmoidf_(g0 + cv * pi);
        float gf = sigmoidf_(g1 + cv * pf);
        float cc = gf * cv + gi * tanhf(g2);
        float go = sigmoidf_(g3 + cc * po);
        float hv = go * tanhf(cc);

        c[sidx] = cc;
        hout[sidx] = __uint_as_float(f2tf32(hv));   // tf32-rounded (conv input only)
        if (yout)
            yout[(((size_t)n * TSTEPS + t) * HC + hc) * HW + px] = hv;
    }
}

// ---------------- host launch (sequential, round-5 structure) ----------------
extern "C" void kernel_launch(void* const* d_in, const int* in_sizes, int n_in,
                              void* d_out, int out_size)
{
    const float* x   = (const float*)d_in[0];
    const float* Wx0 = (const float*)d_in[1];
    const float* bx0 = (const float*)d_in[2];
    const float* Wh0 = (const float*)d_in[3];
    const float* Wp0 = (const float*)d_in[4];
    const float* Wx1 = (const float*)d_in[5];
    const float* bx1 = (const float*)d_in[6];
    const float* Wh1 = (const float*)d_in[7];
    const float* Wp1 = (const float*)d_in[8];
    const float* Wx2 = (const float*)d_in[9];
    const float* bx2 = (const float*)d_in[10];
    const float* Wh2 = (const float*)d_in[11];
    const float* Wp2 = (const float*)d_in[12];
    float* y = (float*)d_out;

    float *gx0, *state, *xtf;
    uint32_t* wt;
    cudaGetSymbolAddress((void**)&gx0,   g_gx0);
    cudaGetSymbolAddress((void**)&state, g_state);
    cudaGetSymbolAddress((void**)&xtf,   g_xtf);
    cudaGetSymbolAddress((void**)&wt,    g_wt);

    float* h0buf[2] = { state + OFF_H0A, state + OFF_H0B };
    float* h1buf[2] = { state + OFF_H1A, state + OFF_H1B };
    float* h2buf[2] = { state + OFF_H2A, state + OFF_H2B };
    float* c0 = state + OFF_C0;
    float* c1 = state + OFF_C1;
    float* c2 = state + OFF_C2;

    init_zero_kernel<<<(NSTATE + 255) / 256, 256>>>(state, NSTATE);

    prep_weights<<<(WSZ_GX0 + 255) / 256, 256>>>(Wx0, CIN0, nullptr, 0, HC0, 24, wt + WOFF_GX0, WSZ_GX0);
    prep_weights<<<(WSZ_L0  + 255) / 256, 256>>>(Wh0, HC0,  nullptr, 0, HC0,  8, wt + WOFF_L0,  WSZ_L0);
    prep_weights<<<(WSZ_L1  + 255) / 256, 256>>>(Wx1, HC0,  Wh1, HC1, HC1, 12, wt + WOFF_L1,  WSZ_L1);
    prep_weights<<<(WSZ_L2  + 255) / 256, 256>>>(Wx2, HC1,  Wh2, HC2, HC2, 12, wt + WOFF_L2,  WSZ_L2);

    const int xN = BATCH * TSTEPS * CIN0 * HW;
    prep_x<<<(xN + 255) / 256, 256>>>(x, xtf, xN);

    // batched gx0 = conv(x_tf32, Wx0) + bx0 over all B*T frames (plain path)
    conv3x3_cell<<<dim3(BATCH * TSTEPS, HC0 / 8, 7), 64>>>(
        xtf, CIN0, (size_t)CIN0 * HW, nullptr, 0, wt + WOFF_GX0, bx0, nullptr, 0,
        HC0, gx0, (size_t)4 * HC0 * HW, nullptr, nullptr, nullptr, nullptr, 0);

    const size_t gx0FrameStride = (size_t)4 * HC0 * HW;           // per t
    const size_t gx0BatchStride = (size_t)TSTEPS * 4 * HC0 * HW;  // per b

    for (int t = 0; t < TSTEPS; ++t) {
        const int rb = t & 1;
        const int wb = rb ^ 1;
        float* h0r = h0buf[rb]; float* h0w = h0buf[wb];
        float* h1r = h1buf[rb]; float* h1w = h1buf[wb];
        float* h2r = h2buf[rb]; float* h2w = h2buf[wb];

        // layer 0: gates = gx0[b,t] + conv(h0_old, Wh0); fused LSTM
        conv3x3_cell<<<dim3(BATCH, HC0 / 8, 7), 64>>>(
            h0r, HC0, (size_t)HC0 * HW, nullptr, 0, wt + WOFF_L0, nullptr,
            gx0 + (size_t)t * gx0FrameStride, gx0BatchStride,
            HC0, nullptr, 0, Wp0, h0w, c0, nullptr, t);

        // layer 1: gates = conv(h0_new, Wx1) + conv(h1_old, Wh1) + bx1
        conv3x3_cell<<<dim3(BATCH, HC1 / 8, 7), 64>>>(
            h0w, HC0, (size_t)HC0 * HW, h1r, HC1, wt + WOFF_L1, bx1, nullptr, 0,
            HC1, nullptr, 0, Wp1, h1w, c1, nullptr, t);

        // layer 2: gates = conv(h1_new, Wx2) + conv(h2_old, Wh2) + bx2; emits y
        conv3x3_cell<<<dim3(BATCH, HC2 / 8, 7), 64>>>(
            h1w, HC1, (size_t)HC1 * HW, h2r, HC2, wt + WOFF_L2, bx2, nullptr, 0,
            HC2, nullptr, 0, Wp2, h2w, c2, y, t);
    }
}

// round 10
// speedup vs baseline: 1.4056x; 1.0465x over previous
#include <cuda_runtime.h>
#include <cuda_bf16.h>
#include <math.h>
#include <stdint.h>

// ---------------- problem constants ----------------
#define BATCH 8
#define TSTEPS 16
#define CIN0 192
#define HC0 64
#define HC1 32
#define HC2 64
#define IMG_H 28
#define IMG_W 28
#define HW 784

// ---------------- device scratch (no allocs allowed) ----------------
__device__ float g_gx0[(size_t)BATCH * TSTEPS * 4 * HC0 * HW];

#define SZ0 (BATCH * HC0 * HW)
#define SZ1 (BATCH * HC1 * HW)
#define SZ2 (BATCH * HC2 * HW)
#define OFF_H0A 0
#define OFF_H0B (OFF_H0A + SZ0)
#define OFF_C0  (OFF_H0B + SZ0)
#define OFF_H1A (OFF_C0  + SZ0)
#define OFF_H1B (OFF_H1A + SZ1)
#define OFF_C1  (OFF_H1B + SZ1)
#define OFF_H2A (OFF_C1  + SZ1)
#define OFF_H2B (OFF_H2A + SZ2)
#define OFF_C2  (OFF_H2B + SZ2)
#define NSTATE  (OFF_C2  + SZ2)
__device__ float g_state[NSTATE];

// pre-transposed tf32 weight buffers, layout [y][chunk][tap][m(32)][ci(8)]
#define WPC 2304
#define WOFF_GX0 0
#define WSZ_GX0 (8 * 24 * WPC)
#define WOFF_L0 (WOFF_GX0 + WSZ_GX0)
#define WSZ_L0  (8 * 8 * WPC)
#define WOFF_L1 (WOFF_L0 + WSZ_L0)
#define WSZ_L1  (4 * 12 * WPC)
#define WOFF_L2 (WOFF_L1 + WSZ_L1)
#define WSZ_L2  (8 * 12 * WPC)
#define WTOTAL  (WOFF_L2 + WSZ_L2)
__device__ uint32_t g_wt[WTOTAL];

__global__ void init_zero_kernel(float* p, int n) {
    int i = blockIdx.x * blockDim.x + threadIdx.x;
    if (i < n) p[i] = 0.f;
}

// ---------------- tf32 helpers ----------------
__device__ __forceinline__ uint32_t f2tf32(float f) {
    uint32_t u;
    asm("cvt.rna.tf32.f32 %0, %1;" : "=r"(u) : "f"(f));
    return u;
}

__device__ __forceinline__ void mma_tf32(float c[4],
                                         uint32_t a0, uint32_t a1, uint32_t a2, uint32_t a3,
                                         uint32_t b0, uint32_t b1) {
    asm volatile(
        "mma.sync.aligned.m16n8k8.row.col.f32.tf32.tf32.f32 "
        "{%0,%1,%2,%3}, {%4,%5,%6,%7}, {%8,%9}, {%0,%1,%2,%3};"
        : "+f"(c[0]), "+f"(c[1]), "+f"(c[2]), "+f"(c[3])
        : "r"(a0), "r"(a1), "r"(a2), "r"(a3), "r"(b0), "r"(b1));
}

__device__ __forceinline__ float sigmoidf_(float x) {
    return 1.0f / (1.0f + __expf(-x));
}

// ---------------- weight prep: transpose + tf32 ----------------
__global__ void prep_weights(const float* __restrict__ WA, int cinA,
                             const float* __restrict__ WB, int cinB,
                             int HC, int chunks, uint32_t* __restrict__ dst, int total)
{
    int idx = blockIdx.x * blockDim.x + threadIdx.x;
    if (idx >= total) return;
    int ci  = idx & 7;
    int m   = (idx >> 3) & 31;
    int tap = (idx >> 8) % 9;
    int chy = idx / WPC;
    int ch  = chy % chunks;
    int y   = chy / chunks;
    int oc  = (m >> 3) * HC + y * 8 + (m & 7);
    int cg  = ch * 8 + ci;
    float w;
    if (cg < cinA) w = WA[((size_t)oc * cinA + cg) * 9 + tap];
    else           w = WB[((size_t)oc * cinB + (cg - cinA)) * 9 + tap];
    dst[idx] = f2tf32(w);
}

// ---------------- conv 3x3 + fused LSTM body (R5 engine, unchanged) ----------
#define SIN_STR 200

struct SmemU {
    union {
        struct {
            uint32_t in[2][8 * SIN_STR];
            uint32_t w[2][WPC];
        } mm;
        float gates[4 * 8 * 112];
    };
};

__device__ __forceinline__ void conv_cell_body(
    SmemU& sm,
    int n, int yb, int rowbase,
    const float* __restrict__ inA, int cinA, size_t inAStride,
    const float* __restrict__ inB, int cinB,
    const uint32_t* __restrict__ wt,
    const float* __restrict__ bias,
    const float* __restrict__ pre, size_t preStride,
    int HC,
    float* __restrict__ out, size_t outStride,   // plain path (hout == nullptr)
    const float* __restrict__ Wp,
    float* __restrict__ hout, float* __restrict__ c,
    float* __restrict__ yout, int t)
{
    const int hcb = yb * 8;

    const int tid    = threadIdx.x;
    const int lane   = tid & 31;
    const int wid    = tid >> 5;
    const int warp_m = wid & 1;
    const int warp_n = wid >> 1;
    const int g      = lane >> 2;
    const int ctg    = lane & 3;

    const int chunks = (cinA + cinB) >> 3;

    int off[7];
#pragma unroll
    for (int s = 0; s < 7; ++s) {
        int nl = warp_n * 56 + s * 8 + g;
        int r = nl / 28;
        off[s] = r * 30 + (nl - r * 28);
    }

    float acc[7][4];
#pragma unroll
    for (int s = 0; s < 7; ++s)
#pragma unroll
        for (int j = 0; j < 4; ++j) acc[s][j] = 0.f;

    float rin[12];
    uint4 rw4[5];

    auto load_chunk = [&](int ch) {
        const int cstart = ch * 8;
        const float* src = (cstart < cinA)
            ? inA + (size_t)n * inAStride + (size_t)cstart * HW
            : inB + ((size_t)n * cinB + (cstart - cinA)) * HW;
#pragma unroll
        for (int k = 0; k < 12; ++k) {
            int idx = tid + k * 128;
            float v = 0.f;
            if (idx < 1440) {
                int ci  = idx / 180;
                int rem = idx - ci * 180;
                int pr  = rem / 30;
                int gr  = rowbase + pr - 1;
                int gc  = (rem - pr * 30) - 1;
                if (gr >= 0 && gr < IMG_H && gc >= 0 && gc < IMG_W)
                    v = src[(size_t)ci * HW + gr * IMG_W + gc];
            }
            rin[k] = v;
        }
        const uint4* wsrc = (const uint4*)(wt + ((size_t)yb * chunks + ch) * WPC);
#pragma unroll
        for (int k = 0; k < 5; ++k) {
            int i4 = tid + k * 128;
            if (i4 < 576) rw4[k] = wsrc[i4];
        }
    };

    load_chunk(0);

    for (int ch = 0; ch < chunks; ++ch) {
        const int st = ch & 1;
#pragma unroll
        for (int k = 0; k < 12; ++k) {
            int idx = tid + k * 128;
            if (idx < 1440) {
                int ci  = idx / 180;
                int rem = idx - ci * 180;
                sm.mm.in[st][ci * SIN_STR + rem] = f2tf32(rin[k]);
            }
        }
#pragma unroll
        for (int k = 0; k < 5; ++k) {
            int i4 = tid + k * 128;
            if (i4 < 576) ((uint4*)sm.mm.w[st])[i4] = rw4[k];
        }
        __syncthreads();

        if (ch + 1 < chunks) load_chunk(ch + 1);

        const uint32_t* win = sm.mm.in[st];
        const uint32_t* ww  = sm.mm.w[st];
#pragma unroll
        for (int kr = 0; kr < 3; ++kr) {
#pragma unroll
            for (int kc = 0; kc < 3; ++kc) {
                const int tap = kr * 3 + kc;
                const uint32_t* wp = ww + tap * 256 + (warp_m * 16 + g) * 8 + ctg;
                uint32_t a0 = wp[0];
                uint32_t a1 = wp[64];
                uint32_t a2 = wp[4];
                uint32_t a3 = wp[68];
                const int bbase = ctg * SIN_STR + kr * 30 + kc;
#pragma unroll
                for (int s = 0; s < 7; ++s) {
                    uint32_t b0 = win[bbase + off[s]];
                    uint32_t b1 = win[bbase + off[s] + 4 * SIN_STR];
                    mma_tf32(acc[s], a0, a1, a2, a3, b0, b1);
                }
            }
        }
    }

    // ---- epilogue ----
    const int m0  = warp_m * 16 + g;
    const int oc0 = (m0 >> 3) * HC + hcb + (m0 & 7);
    const int m1  = m0 + 8;
    const int oc1 = (m1 >> 3) * HC + hcb + (m1 & 7);
    float bv0 = 0.f, bv1 = 0.f;
    if (bias) { bv0 = bias[oc0]; bv1 = bias[oc1]; }

    if (hout == nullptr) {
#pragma unroll
        for (int s = 0; s < 7; ++s) {
#pragma unroll
            for (int j = 0; j < 2; ++j) {
                int nl = warp_n * 56 + s * 8 + 2 * ctg + j;
                int r = nl / 28;
                int px = (rowbase + r) * IMG_W + (nl - r * 28);
                float v0 = acc[s][j]     + bv0;
                float v1 = acc[s][2 + j] + bv1;
                if (pre) {
                    v0 += pre[(size_t)n * preStride + (size_t)oc0 * HW + px];
                    v1 += pre[(size_t)n * preStride + (size_t)oc1 * HW + px];
                }
                out[(size_t)n * outStride + (size_t)oc0 * HW + px] = v0;
                out[(size_t)n * outStride + (size_t)oc1 * HW + px] = v1;
            }
        }
        return;
    }

    __syncthreads();
#pragma unroll
    for (int s = 0; s < 7; ++s) {
#pragma unroll
        for (int j = 0; j < 2; ++j) {
            int nl = warp_n * 56 + s * 8 + 2 * ctg + j;
            float v0 = acc[s][j]     + bv0;
            float v1 = acc[s][2 + j] + bv1;
            if (pre) {
                int r = nl / 28;
                int px = (rowbase + r) * IMG_W + (nl - r * 28);
                v0 += pre[(size_t)n * preStride + (size_t)oc0 * HW + px];
                v1 += pre[(size_t)n * preStride + (size_t)oc1 * HW + px];
            }
            sm.gates[((m0 >> 3) * 8 + (m0 & 7)) * 112 + nl] = v0;
            sm.gates[((m1 >> 3) * 8 + (m1 & 7)) * 112 + nl] = v1;
        }
    }
    __syncthreads();

#pragma unroll
    for (int k = 0; k < 7; ++k) {
        int e   = tid + k * 128;
        int hcl = e / 112;
        int nl  = e - hcl * 112;
        int r   = nl / 28;
        int px  = (rowbase + r) * IMG_W + (nl - r * 28);
        int hc  = hcb + hcl;

        float g0 = sm.gates[(0 * 8 + hcl) * 112 + nl];
        float g1 = sm.gates[(1 * 8 + hcl) * 112 + nl];
        float g2 = sm.gates[(2 * 8 + hcl) * 112 + nl];
        float g3 = sm.gates[(3 * 8 + hcl) * 112 + nl];

        size_t sidx = ((size_t)n * HC + hc) * HW + px;
        float cv = c[sidx];
        float pi = Wp[(size_t)(0 * HC + hc) * HW + px];
        float pf = Wp[(size_t)(1 * HC + hc) * HW + px];
        float po = Wp[(size_t)(2 * HC + hc) * HW + px];

        float gi = sigmoidf_(g0 + cv * pi);
        float gf = sigmoidf_(g1 + cv * pf);
        float cc = gf * cv + gi * tanhf(g2);
        float go = sigmoidf_(g3 + cc * po);
        float hv = go * tanhf(cc);

        c[sidx] = cc;
        hout[sidx] = hv;
        if (yout)
            yout[(((size_t)n * TSTEPS + t) * HC + hc) * HW + px] = hv;
    }
}

// ---------------- standalone conv kernel (gx0(0), L1(t), L2(15)) ------------
__global__ void __launch_bounds__(128, 4) conv3x3_cell(
    const float* __restrict__ inA, int cinA, size_t inAStride,
    const float* __restrict__ inB, int cinB,
    const uint32_t* __restrict__ wt,
    const float* __restrict__ bias,
    const float* __restrict__ pre, size_t preStride,
    int HC,
    float* __restrict__ out, size_t outStride,
    const float* __restrict__ Wp,
    float* __restrict__ hout, float* __restrict__ c,
    float* __restrict__ yout, int t)
{
    __shared__ SmemU sm;
    conv_cell_body(sm, blockIdx.x, blockIdx.y, blockIdx.z * 4,
                   inA, cinA, inAStride, inB, cinB, wt, bias, pre, preStride,
                   HC, out, outStride, Wp, hout, c, yout, t);
}

// ---------------- combo kernel: L0(t) | L2(t-1) | gx0(t+1) in one launch ----
#define GX0_FRAME ((size_t)4 * HC0 * HW)
#define GX0_BSTR  ((size_t)TSTEPS * 4 * HC0 * HW)

__global__ void __launch_bounds__(128, 4) combo_kernel(
    int t,
    const float* __restrict__ x,
    float* __restrict__ gx0,
    float* __restrict__ state,
    const uint32_t* __restrict__ wt,
    const float* __restrict__ bx0, const float* __restrict__ bx2,
    const float* __restrict__ Wp0, const float* __restrict__ Wp2,
    float* __restrict__ y)
{
    __shared__ SmemU sm;

    float* h0buf[2] = { state + OFF_H0A, state + OFF_H0B };
    float* h1buf[2] = { state + OFF_H1A, state + OFF_H1B };
    float* h2buf[2] = { state + OFF_H2A, state + OFF_H2B };

    const int b = blockIdx.x;

    if (b < 448) {
        // ---- L0 at t ----
        int local = b;
        int z = local % 7; local /= 7;
        int yb = local % 8;
        int n  = local / 8;
        const int rb = t & 1, wb = rb ^ 1;
        conv_cell_body(sm, n, yb, z * 4,
                       h0buf[rb], HC0, (size_t)HC0 * HW, nullptr, 0,
                       wt + WOFF_L0, nullptr,
                       gx0 + (size_t)t * GX0_FRAME, GX0_BSTR,
                       HC0, nullptr, 0,
                       Wp0, h0buf[wb], state + OFF_C0, nullptr, t);
    } else if (b < 896) {
        // ---- L2 at t2 = t - 1 ----
        const int t2 = t - 1;
        if (t2 < 0) return;
        int local = b - 448;
        int z = local % 7; local /= 7;
        int yb = local % 8;
        int n  = local / 8;
        const int rb = t2 & 1, wb = rb ^ 1;
        conv_cell_body(sm, n, yb, z * 4,
                       h1buf[wb], HC1, (size_t)HC1 * HW,   // h1(t2), written by L1(t2)
                       h2buf[rb], HC2,
                       wt + WOFF_L2, bx2, nullptr, 0,
                       HC2, nullptr, 0,
                       Wp2, h2buf[wb], state + OFF_C2, y, t2);
    } else {
        // ---- gx0 at tg = t + 1 ----
        const int tg = t + 1;
        if (tg >= TSTEPS) return;
        int local = b - 896;
        int z = local % 7; local /= 7;
        int yb = local % 8;
        int n  = local / 8;
        conv_cell_body(sm, n, yb, z * 4,
                       x + (size_t)tg * CIN0 * HW, CIN0, (size_t)TSTEPS * CIN0 * HW,
                       nullptr, 0,
                       wt + WOFF_GX0, bx0, nullptr, 0,
                       HC0, gx0 + (size_t)tg * GX0_FRAME, GX0_BSTR,
                       nullptr, nullptr, nullptr, nullptr, tg);
    }
}

// ---------------- host launch ----------------
extern "C" void kernel_launch(void* const* d_in, const int* in_sizes, int n_in,
                              void* d_out, int out_size)
{
    const float* x   = (const float*)d_in[0];
    const float* Wx0 = (const float*)d_in[1];
    const float* bx0 = (const float*)d_in[2];
    const float* Wh0 = (const float*)d_in[3];
    const float* Wp0 = (const float*)d_in[4];
    const float* Wx1 = (const float*)d_in[5];
    const float* bx1 = (const float*)d_in[6];
    const float* Wh1 = (const float*)d_in[7];
    const float* Wp1 = (const float*)d_in[8];
    const float* Wx2 = (const float*)d_in[9];
    const float* bx2 = (const float*)d_in[10];
    const float* Wh2 = (const float*)d_in[11];
    const float* Wp2 = (const float*)d_in[12];
    float* y = (float*)d_out;

    float *gx0, *state;
    uint32_t* wt;
    cudaGetSymbolAddress((void**)&gx0,   g_gx0);
    cudaGetSymbolAddress((void**)&state, g_state);
    cudaGetSymbolAddress((void**)&wt,    g_wt);

    float* h0buf[2] = { state + OFF_H0A, state + OFF_H0B };
    float* h1buf[2] = { state + OFF_H1A, state + OFF_H1B };
    float* h2buf[2] = { state + OFF_H2A, state + OFF_H2B };
    float* c1 = state + OFF_C1;

    init_zero_kernel<<<(NSTATE + 255) / 256, 256>>>(state, NSTATE);
    prep_weights<<<(WSZ_GX0 + 255) / 256, 256>>>(Wx0, CIN0, nullptr, 0, HC0, 24, wt + WOFF_GX0, WSZ_GX0);
    prep_weights<<<(WSZ_L0  + 255) / 256, 256>>>(Wh0, HC0,  nullptr, 0, HC0,  8, wt + WOFF_L0,  WSZ_L0);
    prep_weights<<<(WSZ_L1  + 255) / 256, 256>>>(Wx1, HC0,  Wh1, HC1, HC1, 12, wt + WOFF_L1,  WSZ_L1);
    prep_weights<<<(WSZ_L2  + 255) / 256, 256>>>(Wx2, HC1,  Wh2, HC2, HC2, 12, wt + WOFF_L2,  WSZ_L2);

    // prologue: gx0(0)
    conv3x3_cell<<<dim3(BATCH, HC0 / 8, 7), 128>>>(
        x, CIN0, (size_t)TSTEPS * CIN0 * HW, nullptr, 0, wt + WOFF_GX0, bx0, nullptr, 0,
        HC0, gx0, GX0_BSTR, nullptr, nullptr, nullptr, nullptr, 0);

    for (int t = 0; t < TSTEPS; ++t) {
        const int rb = t & 1;
        const int wb = rb ^ 1;

        // launch A: L0(t) || L2(t-1) || gx0(t+1)
        combo_kernel<<<1344, 128>>>(t, x, gx0, state, wt, bx0, bx2, Wp0, Wp2, y);

        // launch B: L1(t) = conv(h0_new, Wx1) + conv(h1_old, Wh1) + bx1; fused
        conv3x3_cell<<<dim3(BATCH, HC1 / 8, 7), 128>>>(
            h0buf[wb], HC0, (size_t)HC0 * HW, h1buf[rb], HC1, wt + WOFF_L1, bx1, nullptr, 0,
            HC1, nullptr, 0, Wp1, h1buf[wb], c1, nullptr, t);
    }

    // epilogue: L2(15)
    {
        const int t2 = TSTEPS - 1;          // 15
        const int rb = t2 & 1, wb = rb ^ 1; // rb=1, wb=0
        conv3x3_cell<<<dim3(BATCH, HC2 / 8, 7), 128>>>(
            h1buf[wb], HC1, (size_t)HC1 * HW, h2buf[rb], HC2, wt + WOFF_L2, bx2, nullptr, 0,
            HC2, nullptr, 0, Wp2, h2buf[wb], state + OFF_C2, y, t2);
    }
}

// round 11
// speedup vs baseline: 1.7145x; 1.2198x over previous
#include <cuda_runtime.h>
#include <cuda_bf16.h>
#include <math.h>
#include <stdint.h>

// ---------------- problem constants ----------------
#define BATCH 8
#define TSTEPS 16
#define CIN0 192
#define HC0 64
#define HC1 32
#define HC2 64
#define IMG_H 28
#define IMG_W 28
#define HW 784

// ---------------- device scratch (no allocs allowed) ----------------
__device__ float g_gx0[(size_t)BATCH * TSTEPS * 4 * HC0 * HW];

#define SZ0 (BATCH * HC0 * HW)
#define SZ1 (BATCH * HC1 * HW)
#define SZ2 (BATCH * HC2 * HW)
#define OFF_H0A 0
#define OFF_H0B (OFF_H0A + SZ0)
#define OFF_C0  (OFF_H0B + SZ0)
#define OFF_H1A (OFF_C0  + SZ0)
#define OFF_H1B (OFF_H1A + SZ1)
#define OFF_C1  (OFF_H1B + SZ1)
#define OFF_H2A (OFF_C1  + SZ1)
#define OFF_H2B (OFF_H2A + SZ2)
#define OFF_C2  (OFF_H2B + SZ2)
#define NSTATE  (OFF_C2  + SZ2)
__device__ float g_state[NSTATE];

// pre-transposed tf32 weight buffers, layout [y][chunk][tap][m(64)][ci(8)]
// oc(m) = (m>>4)*HC + y*16 + (m&15)
#define WPC 4608                       // words per chunk (9*64*8)
#define WOFF_GX0 0
#define WSZ_GX0 (4 * 24 * WPC)         // y=4, chunks=24
#define WOFF_L0 (WOFF_GX0 + WSZ_GX0)
#define WSZ_L0  (4 * 8 * WPC)
#define WOFF_L1 (WOFF_L0 + WSZ_L0)
#define WSZ_L1  (2 * 12 * WPC)
#define WOFF_L2 (WOFF_L1 + WSZ_L1)
#define WSZ_L2  (4 * 12 * WPC)
#define WTOTAL  (WOFF_L2 + WSZ_L2)
__device__ uint32_t g_wt[WTOTAL];

__global__ void init_zero_kernel(float* p, int n) {
    int i = blockIdx.x * blockDim.x + threadIdx.x;
    if (i < n) p[i] = 0.f;
}

// ---------------- tf32 / cp.async helpers ----------------
__device__ __forceinline__ uint32_t f2tf32(float f) {
    uint32_t u;
    asm("cvt.rna.tf32.f32 %0, %1;" : "=r"(u) : "f"(f));
    return u;
}

__device__ __forceinline__ void cp_async16(uint32_t saddr, const void* gaddr) {
    asm volatile("cp.async.cg.shared.global [%0], [%1], 16;" :: "r"(saddr), "l"(gaddr));
}
#define CP_ASYNC_COMMIT() asm volatile("cp.async.commit_group;" ::: "memory")
#define CP_ASYNC_WAIT0()  asm volatile("cp.async.wait_group 0;" ::: "memory")

__device__ __forceinline__ void mma_tf32(float c[4],
                                         uint32_t a0, uint32_t a1, uint32_t a2, uint32_t a3,
                                         uint32_t b0, uint32_t b1) {
    asm volatile(
        "mma.sync.aligned.m16n8k8.row.col.f32.tf32.tf32.f32 "
        "{%0,%1,%2,%3}, {%4,%5,%6,%7}, {%8,%9}, {%0,%1,%2,%3};"
        : "+f"(c[0]), "+f"(c[1]), "+f"(c[2]), "+f"(c[3])
        : "r"(a0), "r"(a1), "r"(a2), "r"(a3), "r"(b0), "r"(b1));
}

__device__ __forceinline__ float sigmoidf_(float x) {
    return 1.0f / (1.0f + __expf(-x));
}

// ---------------- weight prep: transpose + tf32 ----------------
// dst layout: [y][ch][tap][m(64)][ci(8)]; oc = (m>>4)*HC + y*16 + (m&15)
__global__ void prep_weights(const float* __restrict__ WA, int cinA,
                             const float* __restrict__ WB, int cinB,
                             int HC, int chunks, uint32_t* __restrict__ dst, int total)
{
    int idx = blockIdx.x * blockDim.x + threadIdx.x;
    if (idx >= total) return;
    int ci  = idx & 7;
    int m   = (idx >> 3) & 63;
    int tap = (idx >> 9) % 9;
    int chy = idx / WPC;
    int ch  = chy % chunks;
    int y   = chy / chunks;
    int oc  = (m >> 4) * HC + y * 16 + (m & 15);
    int cg  = ch * 8 + ci;
    float w;
    if (cg < cinA) w = WA[((size_t)oc * cinA + cg) * 9 + tap];
    else           w = WB[((size_t)oc * cinB + (cg - cinA)) * 9 + tap];
    dst[idx] = f2tf32(w);
}

// ---------------- conv 3x3 + fused LSTM ----------------
// Block: 128 threads = 4 warps (2 warp_m x 2 warp_n). M=64 per block,
// M=32 PER WARP: each B-fragment feeds 2 MMAs (halves B smem traffic/MMA).
// m -> oc = (m>>4)*HC + yb*16 + (m&15). Weights staged via cp.async.
#define SIN_STR 184   // 184 mod 32 == 24 -> conflict-free B LDS (ctg*24+g distinct)

struct SmemU {
    union {
        struct {
            uint32_t in[2][8 * SIN_STR];  // per stage: 8 cins x (6 rows x 30 cols)
            uint32_t w[2][WPC];           // per stage: [tap][m(64)][ci(8)]
        } mm;                             // 48640 B
        float gates[4 * 16 * 112];        // [gate][hcl(16)][nl]  28672 B
    };
};

__device__ __forceinline__ void conv_cell_body(
    SmemU& sm,
    int n, int yb, int rowbase,
    const float* __restrict__ inA, int cinA, size_t inAStride,
    const float* __restrict__ inB, int cinB,
    const uint32_t* __restrict__ wt,
    const float* __restrict__ bias,
    const float* __restrict__ pre, size_t preStride,
    int HC,
    float* __restrict__ out, size_t outStride,   // plain path (hout == nullptr)
    const float* __restrict__ Wp,
    float* __restrict__ hout, float* __restrict__ c,
    float* __restrict__ yout, int t)
{
    const int hcb = yb * 16;

    const int tid    = threadIdx.x;
    const int lane   = tid & 31;
    const int wid    = tid >> 5;
    const int warp_m = wid & 1;
    const int warp_n = wid >> 1;
    const int g      = lane >> 2;
    const int ctg    = lane & 3;

    const int chunks = (cinA + cinB) >> 3;

    uint32_t wsm[2];
    wsm[0] = (uint32_t)__cvta_generic_to_shared(sm.mm.w[0]);
    wsm[1] = (uint32_t)__cvta_generic_to_shared(sm.mm.w[1]);

    int off[7];
#pragma unroll
    for (int s = 0; s < 7; ++s) {
        int nl = warp_n * 56 + s * 8 + g;
        int r = nl / 28;
        off[s] = r * 30 + (nl - r * 28);
    }

    float acc[7][8];
#pragma unroll
    for (int s = 0; s < 7; ++s)
#pragma unroll
        for (int j = 0; j < 8; ++j) acc[s][j] = 0.f;

    float rin[12];

    auto load_chunk = [&](int ch) {
        const int st = ch & 1;
        const int cstart = ch * 8;
        const float* src = (cstart < cinA)
            ? inA + (size_t)n * inAStride + (size_t)cstart * HW
            : inB + ((size_t)n * cinB + (cstart - cinA)) * HW;
#pragma unroll
        for (int k = 0; k < 12; ++k) {
            int idx = tid + k * 128;
            float v = 0.f;
            if (idx < 1440) {
                int ci  = idx / 180;
                int rem = idx - ci * 180;
                int pr  = rem / 30;
                int gr  = rowbase + pr - 1;
                int gc  = (rem - pr * 30) - 1;
                if (gr >= 0 && gr < IMG_H && gc >= 0 && gc < IMG_W)
                    v = src[(size_t)ci * HW + gr * IMG_W + gc];
            }
            rin[k] = v;
        }
        const char* wsrc = (const char*)(wt + ((size_t)yb * chunks + ch) * WPC);
#pragma unroll
        for (int k = 0; k < 9; ++k) {          // 1152 uint4 = 9 * 128
            int i4 = tid + k * 128;
            cp_async16(wsm[st] + i4 * 16, wsrc + (size_t)i4 * 16);
        }
        CP_ASYNC_COMMIT();
    };

    load_chunk(0);

    for (int ch = 0; ch < chunks; ++ch) {
        const int st = ch & 1;
#pragma unroll
        for (int k = 0; k < 12; ++k) {
            int idx = tid + k * 128;
            if (idx < 1440) {
                int ci  = idx / 180;
                int rem = idx - ci * 180;
                sm.mm.in[st][ci * SIN_STR + rem] = f2tf32(rin[k]);
            }
        }
        CP_ASYNC_WAIT0();                      // weights for chunk ch landed
        __syncthreads();

        if (ch + 1 < chunks) load_chunk(ch + 1);   // overlaps MMA phase

        const uint32_t* win = sm.mm.in[st];
        const uint32_t* ww  = sm.mm.w[st];
#pragma unroll
        for (int kr = 0; kr < 3; ++kr) {
#pragma unroll
            for (int kc = 0; kc < 3; ++kc) {
                const int tap = kr * 3 + kc;
                const uint32_t* wp = ww + tap * 512 + (warp_m * 32 + g) * 8 + ctg;
                uint32_t a00 = wp[0],   a01 = wp[64],  a02 = wp[4],   a03 = wp[68];
                uint32_t a10 = wp[128], a11 = wp[192], a12 = wp[132], a13 = wp[196];
                const int bbase = ctg * SIN_STR + kr * 30 + kc;
#pragma unroll
                for (int s = 0; s < 7; ++s) {
                    uint32_t b0 = win[bbase + off[s]];
                    uint32_t b1 = win[bbase + off[s] + 4 * SIN_STR];
                    mma_tf32(acc[s],     a00, a01, a02, a03, b0, b1);
                    mma_tf32(acc[s] + 4, a10, a11, a12, a13, b0, b1);
                }
            }
        }
    }

    // ---- epilogue: thread owns (gate, hcl) pairs:
    //  acc[s][0..1]: gate=2wm,   hcl=g    ; acc[s][2..3]: gate=2wm,   hcl=g+8
    //  acc[s][4..5]: gate=2wm+1, hcl=g    ; acc[s][6..7]: gate=2wm+1, hcl=g+8
    const int gate0 = 2 * warp_m;
    int ocr[4];
    ocr[0] = gate0 * HC + hcb + g;           // (2wm,   g)
    ocr[1] = gate0 * HC + hcb + g + 8;       // (2wm,   g+8)
    ocr[2] = (gate0 + 1) * HC + hcb + g;     // (2wm+1, g)
    ocr[3] = (gate0 + 1) * HC + hcb + g + 8; // (2wm+1, g+8)
    float bv[4];
#pragma unroll
    for (int f = 0; f < 4; ++f) bv[f] = bias ? bias[ocr[f]] : 0.f;
    const int accidx[4] = {0, 2, 4, 6};

    if (hout == nullptr) {
#pragma unroll
        for (int s = 0; s < 7; ++s) {
#pragma unroll
            for (int j = 0; j < 2; ++j) {
                int nl = warp_n * 56 + s * 8 + 2 * ctg + j;
                int r = nl / 28;
                int px = (rowbase + r) * IMG_W + (nl - r * 28);
#pragma unroll
                for (int f = 0; f < 4; ++f) {
                    float v = acc[s][accidx[f] + j] + bv[f];
                    if (pre) v += pre[(size_t)n * preStride + (size_t)ocr[f] * HW + px];
                    out[(size_t)n * outStride + (size_t)ocr[f] * HW + px] = v;
                }
            }
        }
        return;
    }

    // fused LSTM: exchange gates through smem, then pointwise
    __syncthreads();   // all MMA reads done before union overwrite
    const int hcl0[4] = {g, g + 8, g, g + 8};
    const int gt[4]   = {gate0, gate0, gate0 + 1, gate0 + 1};
#pragma unroll
    for (int s = 0; s < 7; ++s) {
#pragma unroll
        for (int j = 0; j < 2; ++j) {
            int nl = warp_n * 56 + s * 8 + 2 * ctg + j;
            int r = nl / 28;
            int px = (rowbase + r) * IMG_W + (nl - r * 28);
#pragma unroll
            for (int f = 0; f < 4; ++f) {
                float v = acc[s][accidx[f] + j] + bv[f];
                if (pre) v += pre[(size_t)n * preStride + (size_t)ocr[f] * HW + px];
                sm.gates[(gt[f] * 16 + hcl0[f]) * 112 + nl] = v;
            }
        }
    }
    __syncthreads();

    // pointwise over 16 hc x 112 px  (1792 elems, 14 per thread)
#pragma unroll
    for (int k = 0; k < 14; ++k) {
        int e   = tid + k * 128;
        int hcl = e / 112;
        int nl  = e - hcl * 112;
        int r   = nl / 28;
        int px  = (rowbase + r) * IMG_W + (nl - r * 28);
        int hc  = hcb + hcl;

        float g0 = sm.gates[(0 * 16 + hcl) * 112 + nl];
        float g1 = sm.gates[(1 * 16 + hcl) * 112 + nl];
        float g2 = sm.gates[(2 * 16 + hcl) * 112 + nl];
        float g3 = sm.gates[(3 * 16 + hcl) * 112 + nl];

        size_t sidx = ((size_t)n * HC + hc) * HW + px;
        float cv = c[sidx];
        float pi = Wp[(size_t)(0 * HC + hc) * HW + px];
        float pf = Wp[(size_t)(1 * HC + hc) * HW + px];
        float po = Wp[(size_t)(2 * HC + hc) * HW + px];

        float gi = sigmoidf_(g0 + cv * pi);
        float gf = sigmoidf_(g1 + cv * pf);
        float cc = gf * cv + gi * tanhf(g2);
        float go = sigmoidf_(g3 + cc * po);
        float hv = go * tanhf(cc);

        c[sidx] = cc;
        hout[sidx] = hv;
        if (yout)
            yout[(((size_t)n * TSTEPS + t) * HC + hc) * HW + px] = hv;
    }
}

__global__ void __launch_bounds__(128, 4) conv3x3_cell(
    const float* __restrict__ inA, int cinA, size_t inAStride,
    const float* __restrict__ inB, int cinB,
    const uint32_t* __restrict__ wt,
    const float* __restrict__ bias,
    const float* __restrict__ pre, size_t preStride,
    int HC,
    float* __restrict__ out, size_t outStride,
    const float* __restrict__ Wp,
    float* __restrict__ hout, float* __restrict__ c,
    float* __restrict__ yout, int t)
{
    __shared__ SmemU sm;
    conv_cell_body(sm, blockIdx.x, blockIdx.y, blockIdx.z * 4,
                   inA, cinA, inAStride, inB, cinB, wt, bias, pre, preStride,
                   HC, out, outStride, Wp, hout, c, yout, t);
}

// ---------------- host launch (R5 sequential structure) ----------------
extern "C" void kernel_launch(void* const* d_in, const int* in_sizes, int n_in,
                              void* d_out, int out_size)
{
    const float* x   = (const float*)d_in[0];
    const float* Wx0 = (const float*)d_in[1];
    const float* bx0 = (const float*)d_in[2];
    const float* Wh0 = (const float*)d_in[3];
    const float* Wp0 = (const float*)d_in[4];
    const float* Wx1 = (const float*)d_in[5];
    const float* bx1 = (const float*)d_in[6];
    const float* Wh1 = (const float*)d_in[7];
    const float* Wp1 = (const float*)d_in[8];
    const float* Wx2 = (const float*)d_in[9];
    const float* bx2 = (const float*)d_in[10];
    const float* Wh2 = (const float*)d_in[11];
    const float* Wp2 = (const float*)d_in[12];
    float* y = (float*)d_out;

    float *gx0, *state;
    uint32_t* wt;
    cudaGetSymbolAddress((void**)&gx0,   g_gx0);
    cudaGetSymbolAddress((void**)&state, g_state);
    cudaGetSymbolAddress((void**)&wt,    g_wt);

    float* h0buf[2] = { state + OFF_H0A, state + OFF_H0B };
    float* h1buf[2] = { state + OFF_H1A, state + OFF_H1B };
    float* h2buf[2] = { state + OFF_H2A, state + OFF_H2B };
    float* c0 = state + OFF_C0;
    float* c1 = state + OFF_C1;
    float* c2 = state + OFF_C2;

    init_zero_kernel<<<(NSTATE + 255) / 256, 256>>>(state, NSTATE);

    prep_weights<<<(WSZ_GX0 + 255) / 256, 256>>>(Wx0, CIN0, nullptr, 0, HC0, 24, wt + WOFF_GX0, WSZ_GX0);
    prep_weights<<<(WSZ_L0  + 255) / 256, 256>>>(Wh0, HC0,  nullptr, 0, HC0,  8, wt + WOFF_L0,  WSZ_L0);
    prep_weights<<<(WSZ_L1  + 255) / 256, 256>>>(Wx1, HC0,  Wh1, HC1, HC1, 12, wt + WOFF_L1,  WSZ_L1);
    prep_weights<<<(WSZ_L2  + 255) / 256, 256>>>(Wx2, HC1,  Wh2, HC2, HC2, 12, wt + WOFF_L2,  WSZ_L2);

    // batched gx0 = conv(x, Wx0) + bx0 over all B*T frames (plain path)
    conv3x3_cell<<<dim3(BATCH * TSTEPS, HC0 / 16, 7), 128>>>(
        x, CIN0, (size_t)CIN0 * HW, nullptr, 0, wt + WOFF_GX0, bx0, nullptr, 0,
        HC0, gx0, (size_t)4 * HC0 * HW, nullptr, nullptr, nullptr, nullptr, 0);

    const size_t gx0FrameStride = (size_t)4 * HC0 * HW;           // per t
    const size_t gx0BatchStride = (size_t)TSTEPS * 4 * HC0 * HW;  // per b

    for (int t = 0; t < TSTEPS; ++t) {
        const int rb = t & 1;
        const int wb = rb ^ 1;
        float* h0r = h0buf[rb]; float* h0w = h0buf[wb];
        float* h1r = h1buf[rb]; float* h1w = h1buf[wb];
        float* h2r = h2buf[rb]; float* h2w = h2buf[wb];

        // layer 0: gates = gx0[b,t] + conv(h0_old, Wh0); fused LSTM
        conv3x3_cell<<<dim3(BATCH, HC0 / 16, 7), 128>>>(
            h0r, HC0, (size_t)HC0 * HW, nullptr, 0, wt + WOFF_L0, nullptr,
            gx0 + (size_t)t * gx0FrameStride, gx0BatchStride,
            HC0, nullptr, 0, Wp0, h0w, c0, nullptr, t);

        // layer 1: gates = conv(h0_new, Wx1) + conv(h1_old, Wh1) + bx1
        conv3x3_cell<<<dim3(BATCH, HC1 / 16, 7), 128>>>(
            h0w, HC0, (size_t)HC0 * HW, h1r, HC1, wt + WOFF_L1, bx1, nullptr, 0,
            HC1, nullptr, 0, Wp1, h1w, c1, nullptr, t);

        // layer 2: gates = conv(h1_new, Wx2) + conv(h2_old, Wh2) + bx2; emits y
        conv3x3_cell<<<dim3(BATCH, HC2 / 16, 7), 128>>>(
            h1w, HC1, (size_t)HC1 * HW, h2r, HC2, wt + WOFF_L2, bx2, nullptr, 0,
            HC2, nullptr, 0, Wp2, h2w, c2, y, t);
    }
}